// round 17
// baseline (speedup 1.0000x reference)
#include <cuda_runtime.h>
#include <cstdint>
#include <cstddef>

// Fixed shapes: n=512, H=512, B=256
#define BB 256
#define HH 512
#define NN 512
#define GBLK 128      // 8 row-groups (jy; 16 blocks, 32 rows) x 16 col tiles (jx)
#define NTHR 256
#define SP 68         // paired-buffer stride per k (64 payload + 4 pad; mult of 4 -> LDS.128 aligned)
#define SS 34         // scalar-buffer stride per k
// buffers (floats): PA=0, PW0=2176, PW1=4352, PW2=6528; SN aliases PW1 slot
#define PA  0
#define PW0 2176
#define PW1 4352
#define PW2 6528
#define SN  4352
#define NEG_INF (-1.0e9f)
#define F32_TINY 1.17549435e-38f

// -------- device scratch (no allocations allowed) --------
__device__ float    g_h0[2][BB * HH];
__device__ float    g_h1[2][BB * HH];
__device__ float    g_logits[BB * NN];
__device__ int      g_sel[BB];
__device__ unsigned g_avail[BB * (NN / 32)];
__device__ float    g_lp[BB];
__device__ float    g_rowsum[3 * HH];
__device__ unsigned g_bar_cnt;
__device__ unsigned g_bar_gen;
__device__ unsigned g_grp_cnt[8 * 32];    // per-group, 128B apart
__device__ unsigned g_grp_gen[8 * 32];

// -------- Threefry-2x32 (20 rounds), bit-exact JAX replica --------
__device__ __forceinline__ unsigned rotl32(unsigned v, int r) {
    return (v << r) | (v >> (32 - r));
}

__device__ __forceinline__ void tf2x32(unsigned ks0, unsigned ks1,
                                       unsigned x0, unsigned x1,
                                       unsigned& o0, unsigned& o1)
{
    unsigned ks2 = ks0 ^ ks1 ^ 0x1BD11BDAu;
    x0 += ks0; x1 += ks1;
#define TF_R4(a,b,c,d) \
    x0 += x1; x1 = rotl32(x1,(a)); x1 ^= x0; \
    x0 += x1; x1 = rotl32(x1,(b)); x1 ^= x0; \
    x0 += x1; x1 = rotl32(x1,(c)); x1 ^= x0; \
    x0 += x1; x1 = rotl32(x1,(d)); x1 ^= x0;
    TF_R4(13,15,26,6)   x0 += ks1; x1 += ks2 + 1u;
    TF_R4(17,29,16,24)  x0 += ks2; x1 += ks0 + 2u;
    TF_R4(13,15,26,6)   x0 += ks0; x1 += ks1 + 3u;
    TF_R4(17,29,16,24)  x0 += ks1; x1 += ks2 + 4u;
    TF_R4(13,15,26,6)   x0 += ks2; x1 += ks0 + 5u;
#undef TF_R4
    o0 = x0; o1 = x1;
}

// XLA lowers logistic(x) as 0.5 + 0.5*tanh(0.5*x); mirror that op graph.
__device__ __forceinline__ float jax_sigmoid(float x) {
    return __fadd_rn(0.5f, __fmul_rn(0.5f, tanhf(__fmul_rn(0.5f, x))));
}

__device__ __forceinline__ float4 ldcg4(const float* p) {
    return __ldcg(reinterpret_cast<const float4*>(p));
}

// -------- packed f32x2 FMA: two IEEE fp32 FMAs per instruction --------
union f2u { float2 f; unsigned long long u; };

__device__ __forceinline__ float2 ffma2(float2 a, float2 b, float2 c) {
    f2u A, B, C, D;
    A.f = a; B.f = b; C.f = c;
    asm("fma.rn.f32x2 %0, %1, %2, %3;" : "=l"(D.u) : "l"(A.u), "l"(B.u), "l"(C.u));
    return D.f;
}
__device__ __forceinline__ float2 f2lo(float4 v) { return make_float2(v.x, v.y); }
__device__ __forceinline__ float2 f2hi(float4 v) { return make_float2(v.z, v.w); }
__device__ __forceinline__ float2 lds2(const float* p) {
    return *reinterpret_cast<const float2*>(p);
}
__device__ __forceinline__ float4 ld4s(const float* p) {
    return *reinterpret_cast<const float4*>(p);
}
__device__ __forceinline__ void st2(float* p, float a, float b) {
    *reinterpret_cast<float2*>(p) = make_float2(a, b);
}

// paired store: 4 k's of element lr; (u_k, v_k) interleaved at [k][2*lr]
__device__ __forceinline__ void st_pairs(float* buf, int lc, int lr, float4 u, float4 v) {
    st2(buf + (lc + 0) * SP + 2 * lr, u.x, v.x);
    st2(buf + (lc + 1) * SP + 2 * lr, u.y, v.y);
    st2(buf + (lc + 2) * SP + 2 * lr, u.z, v.z);
    st2(buf + (lc + 3) * SP + 2 * lr, u.w, v.w);
}
// scalar store into stride-SS buffer
__device__ __forceinline__ void st_scl(float* buf, int lc, int lr, float4 v) {
    buf[(lc + 0) * SS + lr] = v.x;
    buf[(lc + 1) * SS + lr] = v.y;
    buf[(lc + 2) * SS + lr] = v.z;
    buf[(lc + 3) * SS + lr] = v.w;
}

// -------- barriers --------
__device__ __forceinline__ void gsync_all() {
    __syncthreads();
    if (threadIdx.x == 0) {
        __threadfence();
        unsigned gen = *(volatile unsigned*)&g_bar_gen;
        if (atomicAdd(&g_bar_cnt, 1u) == GBLK - 1u) {
            atomicExch(&g_bar_cnt, 0u);
            __threadfence();
            atomicAdd(&g_bar_gen, 1u);
        } else {
            while (*(volatile unsigned*)&g_bar_gen == gen) { }
        }
        __threadfence();
    }
    __syncthreads();
}

__device__ __forceinline__ void gsync_grp(int gid) {
    __syncthreads();
    if (threadIdx.x == 0) {
        __threadfence();
        unsigned* cnt = &g_grp_cnt[gid * 32];
        unsigned* gen = &g_grp_gen[gid * 32];
        unsigned g0 = *(volatile unsigned*)gen;
        if (atomicAdd(cnt, 1u) == 15u) {
            atomicExch(cnt, 0u);
            __threadfence();
            atomicAdd(gen, 1u);
        } else {
            while (*(volatile unsigned*)gen == g0) { }
        }
        __threadfence();
    }
    __syncthreads();
}

__global__ void __launch_bounds__(NTHR, 1) perm_persistent(
    const float* __restrict__ Wih0, const float* __restrict__ Whh0,
    const float* __restrict__ bih0, const float* __restrict__ bhh0,
    const float* __restrict__ Wih1, const float* __restrict__ Whh1,
    const float* __restrict__ bih1, const float* __restrict__ bhh1,
    const float* __restrict__ Wout, const float* __restrict__ bout,
    float* __restrict__ out)
{
    __shared__ __align__(16) float SM[8704];   // 34.8 KB

    const int blk = blockIdx.x;
    const int tid = threadIdx.x;

    // ---------------- init (per-launch state reset) ----------------
    {
        for (int i = blk * NTHR + tid; i < BB * HH; i += GBLK * NTHR) {
            g_h0[0][i] = 0.0f;
            g_h1[0][i] = 0.0f;
        }
        if (tid < 2) g_lp[2 * blk + tid] = 0.0f;
        if (tid < 32) g_avail[(2 * blk + (tid >> 4)) * 16 + (tid & 15)] = 0xFFFFFFFFu;
        int lane = tid & 31;
        for (int row = blk * 8 + (tid >> 5); row < 3 * HH; row += GBLK * 8) {
            const float* rp = Wih0 + (size_t)row * HH;
            float s = 0.0f;
            for (int k = lane; k < HH; k += 32) s = __fadd_rn(s, rp[k]);
#pragma unroll
            for (int off = 16; off > 0; off >>= 1)
                s = __fadd_rn(s, __shfl_xor_sync(0xFFFFFFFFu, s, off));
            if (lane == 0) g_rowsum[row] = s;
        }
    }
    gsync_all();

    // tile jobs: 8 row-groups (32 rows) x 16 col tiles (32 cols)
    const int jx = blk & 15;
    const int jy = blk >> 4;
    const int gid = jy;
    const int bm0 = jy * 32;
    const int jn0 = jx * 32;
    // compute mapping: warp = (wy rows of 8) x (wx cols of 16); thread = 2 rows x 2 cols
    const int wrp = tid >> 5, lane = tid & 31;
    const int wy = wrp >> 1, wx = wrp & 1;
    const int lty = lane >> 3, ltx = lane & 7;
    const int r0 = wy * 8 + 2 * lty;
    const int c0 = wx * 16 + 2 * ltx;
    // loader mapping (coalesced: 4 rows x 128B per warp)
    const int lr = tid >> 3, lc = (tid & 7) << 2;

    // ---------------- bootstrap: h0n(0) (h0 = 0 -> GEMM term exactly 0) ----------------
    {
        float* h_out = g_h0[1];
#pragma unroll
        for (int mi = 0; mi < 2; mi++) {
            int b = bm0 + r0 + mi;
#pragma unroll
            for (int ni = 0; ni < 2; ni++) {
                int j = jn0 + c0 + ni;
                float ir  = __fadd_rn(__ldcg(&g_rowsum[j]),          bih0[j]);
                float iz  = __fadd_rn(__ldcg(&g_rowsum[j + HH]),     bih0[j + HH]);
                float inn = __fadd_rn(__ldcg(&g_rowsum[j + 2 * HH]), bih0[j + 2 * HH]);
                float hr = __fadd_rn(0.0f, bhh0[j]);
                float hz = __fadd_rn(0.0f, bhh0[j + HH]);
                float hn = __fadd_rn(0.0f, bhh0[j + 2 * HH]);
                float r  = jax_sigmoid(__fadd_rn(ir, hr));
                float z  = jax_sigmoid(__fadd_rn(iz, hz));
                float ng = tanhf(__fadd_rn(inn, __fmul_rn(r, hn)));
                h_out[(size_t)b * HH + j] =
                    __fadd_rn(__fmul_rn(__fsub_rn(1.0f, z), ng), __fmul_rn(z, 0.0f));
            }
        }
    }
    gsync_grp(gid);

    for (int t = 0; t < NN; t++) {
        const int p = t & 1;

        // ===== layer 1 (t): h1n = GRU(h0n(t), h1) ; (x,h)/(wI,wH) pair-interleaved =====
        {
            const float* x_in  = g_h0[p ^ 1];
            const float* h_in  = g_h1[p];
            float*       h_out = g_h1[p ^ 1];

            float2 acc[3][2][2];   // [gate][row mi][col ni], lanes = (I-sum, H-sum)
#pragma unroll
            for (int g = 0; g < 3; g++)
#pragma unroll
                for (int m = 0; m < 2; m++) {
                    acc[g][m][0] = make_float2(0.f, 0.f);
                    acc[g][m][1] = make_float2(0.f, 0.f);
                }
            float4 px = ldcg4(x_in + (size_t)(bm0 + lr) * HH + lc);
            float4 ph = ldcg4(h_in + (size_t)(bm0 + lr) * HH + lc);
            float4 pwi[3], pwh[3];
#pragma unroll
            for (int g = 0; g < 3; g++) {
                pwi[g] = *reinterpret_cast<const float4*>(Wih1 + (size_t)(g * HH + jn0 + lr) * HH + lc);
                pwh[g] = *reinterpret_cast<const float4*>(Whh1 + (size_t)(g * HH + jn0 + lr) * HH + lc);
            }
#pragma unroll 1
            for (int k0 = 0; k0 < HH; k0 += 32) {
                st_pairs(SM + PA, lc, lr, px, ph);
                st_pairs(SM + PW0, lc, lr, pwi[0], pwh[0]);
                st_pairs(SM + PW1, lc, lr, pwi[1], pwh[1]);
                st_pairs(SM + PW2, lc, lr, pwi[2], pwh[2]);
                __syncthreads();
                if (k0 + 32 < HH) {
                    int kn = k0 + 32;
                    px = ldcg4(x_in + (size_t)(bm0 + lr) * HH + kn + lc);
                    ph = ldcg4(h_in + (size_t)(bm0 + lr) * HH + kn + lc);
#pragma unroll
                    for (int g = 0; g < 3; g++) {
                        pwi[g] = *reinterpret_cast<const float4*>(Wih1 + (size_t)(g * HH + jn0 + lr) * HH + kn + lc);
                        pwh[g] = *reinterpret_cast<const float4*>(Whh1 + (size_t)(g * HH + jn0 + lr) * HH + kn + lc);
                    }
                }
#pragma unroll
                for (int k = 0; k < 32; k++) {
                    float4 av = ld4s(SM + PA + k * SP + 2 * r0);   // (x_r0,h_r0,x_r0+1,h_r0+1)
                    float2 a0 = f2lo(av), a1 = f2hi(av);
                    {
                        float4 wv = ld4s(SM + PW0 + k * SP + 2 * c0);
                        acc[0][0][0] = ffma2(a0, f2lo(wv), acc[0][0][0]);
                        acc[0][0][1] = ffma2(a0, f2hi(wv), acc[0][0][1]);
                        acc[0][1][0] = ffma2(a1, f2lo(wv), acc[0][1][0]);
                        acc[0][1][1] = ffma2(a1, f2hi(wv), acc[0][1][1]);
                    }
                    {
                        float4 wv = ld4s(SM + PW1 + k * SP + 2 * c0);
                        acc[1][0][0] = ffma2(a0, f2lo(wv), acc[1][0][0]);
                        acc[1][0][1] = ffma2(a0, f2hi(wv), acc[1][0][1]);
                        acc[1][1][0] = ffma2(a1, f2lo(wv), acc[1][1][0]);
                        acc[1][1][1] = ffma2(a1, f2hi(wv), acc[1][1][1]);
                    }
                    {
                        float4 wv = ld4s(SM + PW2 + k * SP + 2 * c0);
                        acc[2][0][0] = ffma2(a0, f2lo(wv), acc[2][0][0]);
                        acc[2][0][1] = ffma2(a0, f2hi(wv), acc[2][0][1]);
                        acc[2][1][0] = ffma2(a1, f2lo(wv), acc[2][1][0]);
                        acc[2][1][1] = ffma2(a1, f2hi(wv), acc[2][1][1]);
                    }
                }
                __syncthreads();
            }
#pragma unroll
            for (int mi = 0; mi < 2; mi++) {
#pragma unroll
                for (int ni = 0; ni < 2; ni++) {
                    int b = bm0 + r0 + mi;
                    int j = jn0 + c0 + ni;
                    float ir  = __fadd_rn(acc[0][mi][ni].x, bih1[j]);
                    float hr  = __fadd_rn(acc[0][mi][ni].y, bhh1[j]);
                    float iz  = __fadd_rn(acc[1][mi][ni].x, bih1[j + HH]);
                    float hz  = __fadd_rn(acc[1][mi][ni].y, bhh1[j + HH]);
                    float inn = __fadd_rn(acc[2][mi][ni].x, bih1[j + 2 * HH]);
                    float hn  = __fadd_rn(acc[2][mi][ni].y, bhh1[j + 2 * HH]);
                    float r  = jax_sigmoid(__fadd_rn(ir, hr));
                    float z  = jax_sigmoid(__fadd_rn(iz, hz));
                    float ng = tanhf(__fadd_rn(inn, __fmul_rn(r, hn)));
                    float hp = __ldcg(&h_in[(size_t)b * HH + j]);
                    h_out[(size_t)b * HH + j] =
                        __fadd_rn(__fmul_rn(__fsub_rn(1.0f, z), ng), __fmul_rn(z, hp));
                }
            }
        }
        gsync_grp(gid);

        // ===== logits (t) = h1n @ W_out^T + b_out ; act dup + scalar weights =====
        {
            const float* h = g_h1[p ^ 1];
            float2 acc[2];   // [row mi], lanes = (col c0, c0+1)
            acc[0] = make_float2(0.f, 0.f); acc[1] = make_float2(0.f, 0.f);
            float4 pa = ldcg4(h + (size_t)(bm0 + lr) * HH + lc);
            float4 pb = *reinterpret_cast<const float4*>(Wout + (size_t)(jn0 + lr) * HH + lc);
#pragma unroll 1
            for (int k0 = 0; k0 < HH; k0 += 32) {
                st_pairs(SM + PA, lc, lr, pa, pa);
                st_scl(SM + SN, lc, lr, pb);
                __syncthreads();
                if (k0 + 32 < HH) {
                    int kn = k0 + 32;
                    pa = ldcg4(h + (size_t)(bm0 + lr) * HH + kn + lc);
                    pb = *reinterpret_cast<const float4*>(Wout + (size_t)(jn0 + lr) * HH + kn + lc);
                }
#pragma unroll
                for (int k = 0; k < 32; k++) {
                    float4 av = ld4s(SM + PA + k * SP + 2 * r0);   // (a0,a0,a1,a1)
                    float2 a0 = f2lo(av), a1 = f2hi(av);
                    float2 w2 = lds2(SM + SN + k * SS + c0);
                    acc[0] = ffma2(a0, w2, acc[0]);
                    acc[1] = ffma2(a1, w2, acc[1]);
                }
                __syncthreads();
            }
#pragma unroll
            for (int mi = 0; mi < 2; mi++)
#pragma unroll
                for (int ni = 0; ni < 2; ni++) {
                    int b = bm0 + r0 + mi;
                    int c = jn0 + c0 + ni;
                    g_logits[(size_t)b * NN + c] =
                        __fadd_rn(ni ? acc[mi].y : acc[mi].x, bout[c]);
                }
        }
        gsync_grp(gid);

        // ===== phase C: sample(t), then layer0-GEMM(t+1) overlapped =====
        {
            float* W_S = SM;                 // [2][4]
            int*   W_I = (int*)(SM + 8);
            float* W_V = SM + 16;
            float* W_E = SM + 24;
            float* VV  = SM + 64;            // [2][512] masked logits

            const int r    = tid >> 7;
            const int cs0  = tid & 127;
            const int wip  = (tid >> 5) & 3;
            const int b    = 2 * blk + r;

            unsigned sk0, sk1;
            tf2x32(0u, 42u, 0u, (unsigned)t, sk0, sk1);

            float vq[4];
            float bs = -3.4e38f; int bi = 0;
            float lv = -3.4e38f;
#pragma unroll
            for (int q = 0; q < 4; q++) {
                int col = cs0 + 128 * q;
                float lg = __ldcg(&g_logits[(size_t)b * NN + col]);
                unsigned w = g_avail[b * 16 + (col >> 5)];
                float v = ((w >> (col & 31)) & 1u) ? lg : NEG_INF;
                vq[q] = v;
                VV[r * NN + col] = v;
                unsigned o0, o1;
                tf2x32(sk0, sk1, 0u, (unsigned)(b * NN + col), o0, o1);
                unsigned bits = o0 ^ o1;
                float f = __fsub_rn(__uint_as_float((bits >> 9) | 0x3F800000u), 1.0f);
                float gmb = -logf(-logf(fmaxf(f, F32_TINY)));
                float s = __fadd_rn(gmb, v);
                if (s > bs || (s == bs && col < bi)) { bs = s; bi = col; }
                lv = fmaxf(lv, v);
            }
#pragma unroll
            for (int off = 16; off > 0; off >>= 1) {
                float os = __shfl_xor_sync(0xFFFFFFFFu, bs, off);
                int   oi = __shfl_xor_sync(0xFFFFFFFFu, bi, off);
                float ov = __shfl_xor_sync(0xFFFFFFFFu, lv, off);
                if (os > bs || (os == bs && oi < bi)) { bs = os; bi = oi; }
                lv = fmaxf(lv, ov);
            }
            if ((tid & 31) == 0) {
                W_S[r * 4 + wip] = bs; W_I[r * 4 + wip] = bi; W_V[r * 4 + wip] = lv;
            }
            __syncthreads();
            float vmax = W_V[r * 4];
            float fs = W_S[r * 4]; int fi = W_I[r * 4];
#pragma unroll
            for (int w = 1; w < 4; w++) {
                float os = W_S[r * 4 + w]; int oi = W_I[r * 4 + w];
                if (os > fs || (os == fs && oi < fi)) { fs = os; fi = oi; }
                vmax = fmaxf(vmax, W_V[r * 4 + w]);
            }
            float es = 0.0f;
#pragma unroll
            for (int q = 0; q < 4; q++)
                es = __fadd_rn(es, expf(__fsub_rn(vq[q], vmax)));
#pragma unroll
            for (int off = 16; off > 0; off >>= 1)
                es = __fadd_rn(es, __shfl_xor_sync(0xFFFFFFFFu, es, off));
            if ((tid & 31) == 0) W_E[r * 4 + wip] = es;
            __syncthreads();

            if (cs0 == 0) {
                float S = __fadd_rn(__fadd_rn(W_E[r * 4], W_E[r * 4 + 1]),
                                    __fadd_rn(W_E[r * 4 + 2], W_E[r * 4 + 3]));
                int idx = fi;
                float ps = __fdiv_rn(expf(__fsub_rn(VV[r * NN + idx], vmax)), S);
                float lp = __fadd_rn(g_lp[b], logf(__fadd_rn(ps, 1e-9f)));
                g_lp[b]  = lp;
                g_sel[b] = idx;
                g_avail[b * 16 + (idx >> 5)] &= ~(1u << (idx & 31));
                out[(size_t)b * NN * NN + (size_t)t * NN + idx] = 1.0f;
                if (t == NN - 1) out[(size_t)BB * NN * NN + b] = lp;
            }
        }
        __syncthreads();   // SM reuse: sample scratch -> GEMM staging

        // ---- layer0-GEMM(t+1): acc = h0n(t) @ Whh0^T ; (wr,wz) paired + wn scalar ----
        float2 acc_rz[2][2];   // [row mi][col ni], lanes = (r-sum, z-sum)
        float2 acc_n[2];       // [row mi], lanes = (col c0, c0+1)
#pragma unroll
        for (int m = 0; m < 2; m++) {
            acc_rz[m][0] = make_float2(0.f, 0.f);
            acc_rz[m][1] = make_float2(0.f, 0.f);
            acc_n[m]     = make_float2(0.f, 0.f);
        }
        if (t < NN - 1) {
            const float* h_in = g_h0[p ^ 1];   // h0n(t)
            float4 pa = ldcg4(h_in + (size_t)(bm0 + lr) * HH + lc);
            float4 pr = *reinterpret_cast<const float4*>(Whh0 + (size_t)(jn0 + lr) * HH + lc);
            float4 pz = *reinterpret_cast<const float4*>(Whh0 + (size_t)(HH + jn0 + lr) * HH + lc);
            float4 pn = *reinterpret_cast<const float4*>(Whh0 + (size_t)(2 * HH + jn0 + lr) * HH + lc);
#pragma unroll 1
            for (int k0 = 0; k0 < HH; k0 += 32) {
                st_pairs(SM + PA, lc, lr, pa, pa);
                st_pairs(SM + PW0, lc, lr, pr, pz);
                st_scl(SM + SN, lc, lr, pn);
                __syncthreads();
                if (k0 + 32 < HH) {
                    int kn = k0 + 32;
                    pa = ldcg4(h_in + (size_t)(bm0 + lr) * HH + kn + lc);
                    pr = *reinterpret_cast<const float4*>(Whh0 + (size_t)(jn0 + lr) * HH + kn + lc);
                    pz = *reinterpret_cast<const float4*>(Whh0 + (size_t)(HH + jn0 + lr) * HH + kn + lc);
                    pn = *reinterpret_cast<const float4*>(Whh0 + (size_t)(2 * HH + jn0 + lr) * HH + kn + lc);
                }
#pragma unroll
                for (int k = 0; k < 32; k++) {
                    float4 av = ld4s(SM + PA + k * SP + 2 * r0);     // (a0,a0,a1,a1)
                    float2 a0 = f2lo(av), a1 = f2hi(av);
                    float4 wv = ld4s(SM + PW0 + k * SP + 2 * c0);    // (wr0,wz0,wr1,wz1)
                    acc_rz[0][0] = ffma2(a0, f2lo(wv), acc_rz[0][0]);
                    acc_rz[0][1] = ffma2(a0, f2hi(wv), acc_rz[0][1]);
                    acc_rz[1][0] = ffma2(a1, f2lo(wv), acc_rz[1][0]);
                    acc_rz[1][1] = ffma2(a1, f2hi(wv), acc_rz[1][1]);
                    float2 wn2 = lds2(SM + SN + k * SS + c0);        // (wn0,wn1)
                    acc_n[0] = ffma2(a0, wn2, acc_n[0]);
                    acc_n[1] = ffma2(a1, wn2, acc_n[1]);
                }
                __syncthreads();
            }
        }
        gsync_grp(gid);   // publishes sel(t); acc carried in registers

        // ---- layer0 gather + epilogue (t+1): writes h0n(t+1) ----
        if (t < NN - 1) {
            const float* h_in = g_h0[p ^ 1];
            float*       h_out = g_h0[p];
#pragma unroll
            for (int mi = 0; mi < 2; mi++) {
                int b = bm0 + r0 + mi;
                int xs = __ldcg(&g_sel[b]);
#pragma unroll
                for (int ni = 0; ni < 2; ni++) {
                    int j = jn0 + c0 + ni;
                    float ir  = __ldg(&Wih0[(size_t)j * HH + xs]);
                    float iz  = __ldg(&Wih0[(size_t)(j + HH) * HH + xs]);
                    float inn = __ldg(&Wih0[(size_t)(j + 2 * HH) * HH + xs]);
                    ir  = __fadd_rn(ir,  bih0[j]);
                    iz  = __fadd_rn(iz,  bih0[j + HH]);
                    inn = __fadd_rn(inn, bih0[j + 2 * HH]);
                    float hr = __fadd_rn(acc_rz[mi][ni].x, bhh0[j]);
                    float hz = __fadd_rn(acc_rz[mi][ni].y, bhh0[j + HH]);
                    float hn = __fadd_rn(ni ? acc_n[mi].y : acc_n[mi].x, bhh0[j + 2 * HH]);
                    float r  = jax_sigmoid(__fadd_rn(ir, hr));
                    float z  = jax_sigmoid(__fadd_rn(iz, hz));
                    float ng = tanhf(__fadd_rn(inn, __fmul_rn(r, hn)));
                    float hp = __ldcg(&h_in[(size_t)b * HH + j]);
                    h_out[(size_t)b * HH + j] =
                        __fadd_rn(__fmul_rn(__fsub_rn(1.0f, z), ng), __fmul_rn(z, hp));
                }
            }
            gsync_grp(gid);
        }
    }
}

// -------- host launcher: 2 graph nodes (memset + persistent kernel) --------
extern "C" void kernel_launch(void* const* d_in, const int* in_sizes, int n_in,
                              void* d_out, int out_size)
{
    int base = (n_in == 11) ? 1 : 0;   // batch_size scalar first per metadata
    const float* Wih0 = (const float*)d_in[base + 0];
    const float* Whh0 = (const float*)d_in[base + 1];
    const float* bih0 = (const float*)d_in[base + 2];
    const float* bhh0 = (const float*)d_in[base + 3];
    const float* Wih1 = (const float*)d_in[base + 4];
    const float* Whh1 = (const float*)d_in[base + 5];
    const float* bih1 = (const float*)d_in[base + 6];
    const float* bhh1 = (const float*)d_in[base + 7];
    const float* Wout = (const float*)d_in[base + 8];
    const float* bout = (const float*)d_in[base + 9];
    float* out = (float*)d_out;
    (void)in_sizes;

    cudaMemsetAsync(d_out, 0, (size_t)out_size * sizeof(float), 0);
    perm_persistent<<<GBLK, NTHR>>>(Wih0, Whh0, bih0, bhh0,
                                    Wih1, Whh1, bih1, bhh1,
                                    Wout, bout, out);
}